// round 2
// baseline (speedup 1.0000x reference)
#include <cuda_runtime.h>

#define LEAK   0.1f
#define BN_EPS 1e-5f

// problem dims
#define B_   16
#define CH   32          // inp == oup
#define H0c  48
#define H2c  46
#define H3c  44
#define D0   2304        // 48*48
#define D1   2116        // 46*46
#define D2   1936        // 44*44
#define NF   512         // feature codebook size
#define BI   512         // B*CH
#define OC   1024        // CH*CH
#define BOC  16384       // B*CH*CH

// ---------------- scratch (static device memory; no allocations) ----------------
__device__ float g_S0[NF * NF];
__device__ float g_S1[NF * NF];
__device__ float g_DOT1[NF * NF];
__device__ float g_h1[BI * D1];
__device__ float g_Cs[9 * NF * D2];     // shifted cb_fdw2 copies
__device__ float g_G[9 * NF * NF];      // G[t][k][m]
__device__ float g_T[NF * CH * NF];     // T[k][o][m]
__device__ float g_A[BI * NF];          // A[bg][m]
__device__ int   g_cnt[B_ * CH * NF];
__device__ int   g_idx0[BI];
__device__ int   g_idx1[BI];
__device__ int   g_idx2[BOC];
__device__ int   g_idx3[BOC];
__device__ float g_qw1[CH * 9];
__device__ float g_qw2[CH * 9];
__device__ float g_qpw1[OC];
__device__ float g_qpw2[OC];
__device__ float g_nfdw[NF];
__device__ float g_nfpw[NF];
__device__ float g_nfdw2[NF];
__device__ float g_nfpw2[NF];

// ---------------- codebook row norms ----------------
__global__ void norms_kernel(const float* __restrict__ fdw, const float* __restrict__ fpw,
                             const float* __restrict__ fdw2, const float* __restrict__ fpw2) {
    int row = blockIdx.x;
    int which = blockIdx.y;
    const float* src; int D; float* dst;
    if (which == 0)      { src = fdw;  D = D0; dst = g_nfdw;  }
    else if (which == 1) { src = fpw;  D = D1; dst = g_nfpw;  }
    else if (which == 2) { src = fdw2; D = D1; dst = g_nfdw2; }
    else                 { src = fpw2; D = D2; dst = g_nfpw2; }
    const float* p = src + (long)row * D;
    float s = 0.f;
    for (int i = threadIdx.x; i < D; i += 256) { float v = p[i]; s += v * v; }
    __shared__ float sm[256];
    sm[threadIdx.x] = s; __syncthreads();
    for (int o = 128; o > 0; o >>= 1) {
        if (threadIdx.x < o) sm[threadIdx.x] += sm[threadIdx.x + o];
        __syncthreads();
    }
    if (threadIdx.x == 0) dst[row] = sm[0];
}

// ---------------- weight VQ (tiny) ----------------
__global__ void quantw_kernel(const float* __restrict__ dw1, const float* __restrict__ pw1,
                              const float* __restrict__ dw2, const float* __restrict__ pw2,
                              const float* __restrict__ cdw, const float* __restrict__ cpw,
                              const float* __restrict__ cdw2, const float* __restrict__ cpw2) {
    int t = threadIdx.x;
    if (t < 32) {
        float w[9];
        for (int j = 0; j < 9; j++) w[j] = dw1[t * 9 + j];
        float bd = 3.4e38f; int bk = 0;
        for (int k = 0; k < 256; k++) {
            float d = 0.f;
            for (int j = 0; j < 9; j++) { float e = w[j] - cdw[k * 9 + j]; d += e * e; }
            if (d < bd) { bd = d; bk = k; }
        }
        for (int j = 0; j < 9; j++) g_qw1[t * 9 + j] = cdw[bk * 9 + j];
        for (int j = 0; j < 9; j++) w[j] = dw2[t * 9 + j];
        bd = 3.4e38f; bk = 0;
        for (int k = 0; k < 256; k++) {
            float d = 0.f;
            for (int j = 0; j < 9; j++) { float e = w[j] - cdw2[k * 9 + j]; d += e * e; }
            if (d < bd) { bd = d; bk = k; }
        }
        for (int j = 0; j < 9; j++) g_qw2[t * 9 + j] = cdw2[bk * 9 + j];
    }
    for (int c = t; c < OC; c += 256) {
        float w = pw1[c]; float bd = 3.4e38f; int bk = 0;
        for (int k = 0; k < 256; k++) { float e = w - cpw[k]; float d = e * e; if (d < bd) { bd = d; bk = k; } }
        g_qpw1[c] = cpw[bk];
        w = pw2[c]; bd = 3.4e38f; bk = 0;
        for (int k = 0; k < 256; k++) { float e = w - cpw2[k]; float d = e * e; if (d < bd) { bd = d; bk = k; } }
        g_qpw2[c] = cpw2[bk];
    }
}

// ---------------- C = A (MxK) * B^T (NxK), z-batched; M,N multiples of 64, K%4==0 ----------------
__global__ void gemm_nt(const float* __restrict__ A, const float* __restrict__ Bm, float* __restrict__ C,
                        int M, int N, int K, long sAz, long sBz, long sCz) {
    A += blockIdx.z * sAz; Bm += blockIdx.z * sBz; C += blockIdx.z * sCz;
    __shared__ float As[16][64];
    __shared__ float Bs[16][64];
    int tid = threadIdx.y * 16 + threadIdx.x;
    int m0 = blockIdx.y * 64, n0 = blockIdx.x * 64;
    int lr = tid >> 2;
    int lk = (tid & 3) * 4;
    float acc[4][4] = {};
    for (int k0 = 0; k0 < K; k0 += 16) {
        float4 a4 = make_float4(0.f, 0.f, 0.f, 0.f), b4 = make_float4(0.f, 0.f, 0.f, 0.f);
        if (k0 + lk < K) {
            a4 = *(const float4*)(A + (long)(m0 + lr) * K + k0 + lk);
            b4 = *(const float4*)(Bm + (long)(n0 + lr) * K + k0 + lk);
        }
        As[lk + 0][lr] = a4.x; As[lk + 1][lr] = a4.y; As[lk + 2][lr] = a4.z; As[lk + 3][lr] = a4.w;
        Bs[lk + 0][lr] = b4.x; Bs[lk + 1][lr] = b4.y; Bs[lk + 2][lr] = b4.z; Bs[lk + 3][lr] = b4.w;
        __syncthreads();
#pragma unroll
        for (int kk = 0; kk < 16; kk++) {
            float4 av = *(const float4*)&As[kk][threadIdx.y * 4];
            float4 bv = *(const float4*)&Bs[kk][threadIdx.x * 4];
            float a_[4] = { av.x, av.y, av.z, av.w };
            float b_[4] = { bv.x, bv.y, bv.z, bv.w };
#pragma unroll
            for (int i = 0; i < 4; i++)
#pragma unroll
                for (int j = 0; j < 4; j++) acc[i][j] += a_[i] * b_[j];
        }
        __syncthreads();
    }
#pragma unroll
    for (int i = 0; i < 4; i++) {
        int m = m0 + threadIdx.y * 4 + i;
#pragma unroll
        for (int j = 0; j < 4; j++)
            C[(long)m * N + n0 + threadIdx.x * 4 + j] = acc[i][j];
    }
}

// ---------------- C = A (MxK) * B (KxN), fused BN + LeakyReLU; K%16==0, N%4==0 ----------------
__global__ void gemm_nn_bn(const float* __restrict__ A, const float* __restrict__ Bm, float* __restrict__ C,
                           int M, int N, int K,
                           const float* __restrict__ gamma, const float* __restrict__ beta,
                           const float* __restrict__ rmean, const float* __restrict__ rvar) {
    __shared__ float As[16][64];
    __shared__ float Bs[16][64];
    int tid = threadIdx.y * 16 + threadIdx.x;
    int m0 = blockIdx.y * 64, n0 = blockIdx.x * 64;
    int lr = tid >> 2;
    int lk = (tid & 3) * 4;
    int kb = tid >> 4;
    int nb = (tid & 15) * 4;
    float acc[4][4] = {};
    for (int k0 = 0; k0 < K; k0 += 16) {
        float4 a4 = *(const float4*)(A + (long)(m0 + lr) * K + k0 + lk);
        As[lk + 0][lr] = a4.x; As[lk + 1][lr] = a4.y; As[lk + 2][lr] = a4.z; As[lk + 3][lr] = a4.w;
        float4 b4 = make_float4(0.f, 0.f, 0.f, 0.f);
        if (n0 + nb < N) b4 = *(const float4*)(Bm + (long)(k0 + kb) * N + n0 + nb);
        Bs[kb][nb + 0] = b4.x; Bs[kb][nb + 1] = b4.y; Bs[kb][nb + 2] = b4.z; Bs[kb][nb + 3] = b4.w;
        __syncthreads();
#pragma unroll
        for (int kk = 0; kk < 16; kk++) {
            float4 av = *(const float4*)&As[kk][threadIdx.y * 4];
            float4 bv = *(const float4*)&Bs[kk][threadIdx.x * 4];
            float a_[4] = { av.x, av.y, av.z, av.w };
            float b_[4] = { bv.x, bv.y, bv.z, bv.w };
#pragma unroll
            for (int i = 0; i < 4; i++)
#pragma unroll
                for (int j = 0; j < 4; j++) acc[i][j] += a_[i] * b_[j];
        }
        __syncthreads();
    }
#pragma unroll
    for (int i = 0; i < 4; i++) {
        int m = m0 + threadIdx.y * 4 + i;
        int g = m & 31;
        float sc = rsqrtf(rvar[g] + BN_EPS) * gamma[g];
        float mu = rmean[g], bt = beta[g];
#pragma unroll
        for (int j = 0; j < 4; j++) {
            int n = n0 + threadIdx.x * 4 + j;
            if (n < N) {
                float v = (acc[i][j] - mu) * sc + bt;
                C[(long)m * N + n] = (v >= 0.f) ? v : LEAK * v;
            }
        }
    }
}

// ---------------- row-wise argmin of (norms[k] - 2*S[row,k]) ----------------
__global__ void argmin_rows(const float* __restrict__ S, const float* __restrict__ norms,
                            int* __restrict__ out, int N) {
    int row = blockIdx.x;
    const float* s = S + (long)row * N;
    float bd = 3.4e38f; int bk = 0;
    for (int k = threadIdx.x; k < N; k += 256) {
        float d = norms[k] - 2.0f * s[k];
        if (d < bd) { bd = d; bk = k; }
    }
    __shared__ float sd[256]; __shared__ int si[256];
    sd[threadIdx.x] = bd; si[threadIdx.x] = bk; __syncthreads();
    for (int o = 128; o > 0; o >>= 1) {
        if (threadIdx.x < o) {
            float d2 = sd[threadIdx.x + o]; int k2 = si[threadIdx.x + o];
            if (d2 < sd[threadIdx.x] || (d2 == sd[threadIdx.x] && k2 < si[threadIdx.x])) {
                sd[threadIdx.x] = d2; si[threadIdx.x] = k2;
            }
        }
        __syncthreads();
    }
    if (threadIdx.x == 0) out[row] = si[0];
}

// ---------------- conv1: h1[v] = lrelu(conv3x3(cb_fdw[idx0[v]], qw1[v%32])) ----------------
__global__ void conv1_lrelu(const float* __restrict__ cb_fdw) {
    int v = blockIdx.x;
    int i = v & 31;
    __shared__ float w[9];
    if (threadIdx.x < 9) w[threadIdx.x] = g_qw1[i * 9 + threadIdx.x];
    __syncthreads();
    const float* src = cb_fdw + (long)g_idx0[v] * D0;
    for (int p = threadIdx.x; p < D1; p += 256) {
        int py = p / H2c, px = p - py * H2c;
        const float* s0 = src + py * H0c + px;
        float acc = s0[0] * w[0] + s0[1] * w[1] + s0[2] * w[2]
                  + s0[H0c] * w[3] + s0[H0c + 1] * w[4] + s0[H0c + 2] * w[5]
                  + s0[2 * H0c] * w[6] + s0[2 * H0c + 1] * w[7] + s0[2 * H0c + 2] * w[8];
        g_h1[(long)v * D1 + p] = (acc >= 0.f) ? acc : LEAK * acc;
    }
}

// ---------------- idx2: argmin_k (||c_k||^2 - 2 s DOT1[j,k]) for 16384 (b,c') rows ----------------
__global__ void idx2_kernel() {
    int vbi = blockIdx.x;           // b*32 + i
    int b = vbi >> 5, i = vbi & 31;
    int j = g_idx1[vbi];
    __shared__ float dr[NF]; __shared__ float nn[NF];
    for (int k = threadIdx.x; k < NF; k += 256) {
        dr[k] = g_DOT1[(long)j * NF + k];
        nn[k] = g_nfdw2[k];
    }
    __syncthreads();
    if (threadIdx.x < 32) {
        int o = threadIdx.x;
        float s = g_qpw1[o * 32 + i];
        float bd = 3.4e38f; int bk = 0;
        for (int k = 0; k < NF; k++) {
            float d = nn[k] - 2.0f * s * dr[k];
            if (d < bd) { bd = d; bk = k; }
        }
        g_idx2[b * OC + o * 32 + i] = bk;
    }
}

// ---------------- shifted copies of cb_fdw2 for the G GEMMs ----------------
__global__ void shift_prep(const float* __restrict__ cb_fdw2) {
    int k = blockIdx.x, t = blockIdx.y;
    int ty = t / 3, tx = t - ty * 3;
    const float* src = cb_fdw2 + (long)k * D1;
    float* dst = g_Cs + ((long)t * NF + k) * D2;
    for (int p = threadIdx.x; p < D2; p += 256) {
        int py = p / H3c, px = p - py * H3c;
        dst[p] = src[(py + ty) * H2c + px + tx];
    }
}

// ---------------- T[k][o][m] = sum_t qw2[o][t] * G[t][k][m] ----------------
__global__ void T_kernel() {
    int k = blockIdx.x;
    __shared__ float gs[9][NF];
    __shared__ float ws[CH][9];
    for (int t = 0; t < 9; t++)
        for (int m = threadIdx.x; m < NF; m += 256)
            gs[t][m] = g_G[((long)t * NF + k) * NF + m];
    for (int idx = threadIdx.x; idx < CH * 9; idx += 256)
        ws[idx / 9][idx % 9] = g_qw2[idx];
    __syncthreads();
    for (int om = threadIdx.x; om < CH * NF; om += 256) {
        int o = om >> 9, m = om & (NF - 1);
        float acc = 0.f;
#pragma unroll
        for (int t = 0; t < 9; t++) acc += ws[o][t] * gs[t][m];
        g_T[((long)k * CH + o) * NF + m] = acc;
    }
}

// ---------------- idx3: one warp per (b,c') row ----------------
__global__ void idx3_kernel() {
    int gwarp = (blockIdx.x * blockDim.x + threadIdx.x) >> 5;
    int lane = threadIdx.x & 31;
    if (gwarp >= BOC) return;
    int r = gwarp;
    int k = g_idx2[r];
    int cpr = r & (OC - 1);
    int o = cpr >> 5;
    const float* Tr = g_T + ((long)k * CH + o) * NF;
    float bd = 3.4e38f; int bk = 0;
    for (int m = lane; m < NF; m += 32) {
        float d = g_nfpw2[m] - 2.0f * Tr[m];
        if (d < bd) { bd = d; bk = m; }
    }
    for (int off = 16; off > 0; off >>= 1) {
        float d2 = __shfl_down_sync(0xffffffffu, bd, off);
        int k2 = __shfl_down_sync(0xffffffffu, bk, off);
        if (d2 < bd || (d2 == bd && k2 < bk)) { bd = d2; bk = k2; }
    }
    if (lane == 0) g_idx3[r] = bk;
}

// ---------------- histogram of idx3 per (b,o) (deterministic, serial per block) ----------------
__global__ void cnt_kernel() {
    int bo = blockIdx.x;  // b*32+o
    __shared__ int c[NF];
    for (int m = threadIdx.x; m < NF; m += 256) c[m] = 0;
    __syncthreads();
    if (threadIdx.x == 0) {
        int b = bo >> 5, o = bo & 31;
        for (int i = 0; i < 32; i++) c[g_idx3[b * OC + o * 32 + i]]++;
    }
    __syncthreads();
    for (int m = threadIdx.x; m < NF; m += 256) g_cnt[(long)bo * NF + m] = c[m];
}

// ---------------- A[bg][m] = sum_o qpw2[g*32+o] * cnt[b][o][m] ----------------
__global__ void A_kernel() {
    int bg = blockIdx.x;
    int b = bg >> 5, g = bg & 31;
    __shared__ float w[32];
    if (threadIdx.x < 32) w[threadIdx.x] = g_qpw2[g * 32 + threadIdx.x];
    __syncthreads();
    for (int m = threadIdx.x; m < NF; m += 256) {
        float acc = 0.f;
#pragma unroll
        for (int o = 0; o < 32; o++)
            acc += w[o] * (float)g_cnt[((long)(b * 32 + o)) * NF + m];
        g_A[(long)bg * NF + m] = acc;
    }
}

extern "C" void kernel_launch(void* const* d_in, const int* in_sizes, int n_in,
                              void* d_out, int out_size) {
    const float* x       = (const float*)d_in[0];
    const float* dw_w1   = (const float*)d_in[1];
    const float* pw_w1   = (const float*)d_in[2];
    const float* dw_w2   = (const float*)d_in[3];
    const float* pw_w2   = (const float*)d_in[4];
    const float* cb_dw   = (const float*)d_in[5];
    const float* cb_pw   = (const float*)d_in[6];
    const float* cb_dw2  = (const float*)d_in[7];
    const float* cb_pw2  = (const float*)d_in[8];
    const float* cb_fdw  = (const float*)d_in[9];
    const float* cb_fpw  = (const float*)d_in[10];
    const float* cb_fdw2 = (const float*)d_in[11];
    const float* cb_fpw2 = (const float*)d_in[12];
    const float* gamma   = (const float*)d_in[13];
    const float* beta    = (const float*)d_in[14];
    const float* rmean   = (const float*)d_in[15];
    const float* rvar    = (const float*)d_in[16];
    float* out = (float*)d_out;

    float *pS0, *pS1, *pDOT1, *ph1, *pCs, *pG, *pA;
    cudaGetSymbolAddress((void**)&pS0, g_S0);
    cudaGetSymbolAddress((void**)&pS1, g_S1);
    cudaGetSymbolAddress((void**)&pDOT1, g_DOT1);
    cudaGetSymbolAddress((void**)&ph1, g_h1);
    cudaGetSymbolAddress((void**)&pCs, g_Cs);
    cudaGetSymbolAddress((void**)&pG, g_G);
    cudaGetSymbolAddress((void**)&pA, g_A);
    int *pidx0, *pidx1;
    cudaGetSymbolAddress((void**)&pidx0, g_idx0);
    cudaGetSymbolAddress((void**)&pidx1, g_idx1);
    float *pnfdw, *pnfpw;
    cudaGetSymbolAddress((void**)&pnfdw, g_nfdw);
    cudaGetSymbolAddress((void**)&pnfpw, g_nfpw);

    dim3 blk2(16, 16);

    // norms + weight VQ
    norms_kernel<<<dim3(NF, 4), 256>>>(cb_fdw, cb_fpw, cb_fdw2, cb_fpw2);
    quantw_kernel<<<1, 256>>>(dw_w1, pw_w1, dw_w2, pw_w2, cb_dw, cb_pw, cb_dw2, cb_pw2);

    // stage A: VQ0
    gemm_nt<<<dim3(8, 8, 1), blk2>>>(x, cb_fdw, pS0, BI, NF, D0, 0, 0, 0);
    argmin_rows<<<BI, 256>>>(pS0, pnfdw, pidx0, NF);

    // stage B: dwconv1 + lrelu
    conv1_lrelu<<<BI, 256>>>(cb_fdw);

    // stage C: VQ1
    gemm_nt<<<dim3(8, 8, 1), blk2>>>(ph1, cb_fpw, pS1, BI, NF, D1, 0, 0, 0);
    argmin_rows<<<BI, 256>>>(pS1, pnfpw, pidx1, NF);

    // stage E: idx2 via DOT1 table
    gemm_nt<<<dim3(8, 8, 1), blk2>>>(cb_fpw, cb_fdw2, pDOT1, NF, NF, D1, 0, 0, 0);
    idx2_kernel<<<BI, 256>>>();

    // stage F: G (9 shifted GEMMs) -> T -> idx3
    shift_prep<<<dim3(NF, 9), 256>>>(cb_fdw2);
    gemm_nt<<<dim3(8, 8, 9), blk2>>>(pCs, cb_fpw2, pG, NF, NF, D2,
                                     (long)NF * D2, 0, (long)NF * NF);
    T_kernel<<<NF, 256>>>();
    idx3_kernel<<<(BOC * 32) / 256, 256>>>();

    // stage G: histogram -> A -> output GEMM with fused BN + lrelu
    cnt_kernel<<<B_ * CH, 256>>>();
    A_kernel<<<BI, 256>>>();
    gemm_nn_bn<<<dim3((D2 + 63) / 64, BI / 64), blk2>>>(pA, cb_fpw2, out, BI, D2, NF,
                                                        gamma, beta, rmean, rvar);
}

// round 3
// speedup vs baseline: 1.6651x; 1.6651x over previous
#include <cuda_runtime.h>

#define LEAK   0.1f
#define BN_EPS 1e-5f

// problem dims
#define B_   16
#define CH   32          // inp == oup
#define H0c  48
#define H2c  46
#define H3c  44
#define D0   2304        // 48*48
#define D1   2116        // 46*46
#define D2   1936        // 44*44
#define NF   512         // feature codebook size
#define BI   512         // B*CH
#define OC   1024        // CH*CH
#define BOC  16384       // B*CH*CH

// ---------------- scratch (static device memory; no allocations) ----------------
__device__ float g_Sp[8 * NF * NF];     // split-K partials (reused for S0, S1, DOT1)
__device__ float g_Gp[18 * NF * NF];    // G partials: z = t*2 + s
__device__ float g_h1[BI * D1];
__device__ float g_Cs[9 * NF * D2];     // shifted cb_fdw2 copies
__device__ float g_A[BI * NF];          // A[bg][m]
__device__ int   g_cnt[B_ * CH * NF];
__device__ int   g_idx0[BI];
__device__ int   g_idx1[BI];
__device__ int   g_idx2[BOC];
__device__ int   g_pair[NF * CH];       // idx3 per (k,o) pair
__device__ float g_qw1[CH * 9];
__device__ float g_qw2[CH * 9];
__device__ float g_qpw1[OC];
__device__ float g_qpw2[OC];
__device__ float g_nfdw[NF];
__device__ float g_nfpw[NF];
__device__ float g_nfdw2[NF];
__device__ float g_nfpw2[NF];

// ---------------- codebook row norms ----------------
__global__ void norms_kernel(const float* __restrict__ fdw, const float* __restrict__ fpw,
                             const float* __restrict__ fdw2, const float* __restrict__ fpw2) {
    int row = blockIdx.x;
    int which = blockIdx.y;
    const float* src; int D; float* dst;
    if (which == 0)      { src = fdw;  D = D0; dst = g_nfdw;  }
    else if (which == 1) { src = fpw;  D = D1; dst = g_nfpw;  }
    else if (which == 2) { src = fdw2; D = D1; dst = g_nfdw2; }
    else                 { src = fpw2; D = D2; dst = g_nfpw2; }
    const float* p = src + (long)row * D;
    float s = 0.f;
    for (int i = threadIdx.x; i < D; i += 256) { float v = p[i]; s += v * v; }
    __shared__ float sm[256];
    sm[threadIdx.x] = s; __syncthreads();
    for (int o = 128; o > 0; o >>= 1) {
        if (threadIdx.x < o) sm[threadIdx.x] += sm[threadIdx.x + o];
        __syncthreads();
    }
    if (threadIdx.x == 0) dst[row] = sm[0];
}

// ---------------- weight VQ (tiny) ----------------
__global__ void quantw_kernel(const float* __restrict__ dw1, const float* __restrict__ pw1,
                              const float* __restrict__ dw2, const float* __restrict__ pw2,
                              const float* __restrict__ cdw, const float* __restrict__ cpw,
                              const float* __restrict__ cdw2, const float* __restrict__ cpw2) {
    int t = threadIdx.x;
    if (t < 32) {
        float w[9];
        for (int j = 0; j < 9; j++) w[j] = dw1[t * 9 + j];
        float bd = 3.4e38f; int bk = 0;
        for (int k = 0; k < 256; k++) {
            float d = 0.f;
            for (int j = 0; j < 9; j++) { float e = w[j] - cdw[k * 9 + j]; d += e * e; }
            if (d < bd) { bd = d; bk = k; }
        }
        for (int j = 0; j < 9; j++) g_qw1[t * 9 + j] = cdw[bk * 9 + j];
        for (int j = 0; j < 9; j++) w[j] = dw2[t * 9 + j];
        bd = 3.4e38f; bk = 0;
        for (int k = 0; k < 256; k++) {
            float d = 0.f;
            for (int j = 0; j < 9; j++) { float e = w[j] - cdw2[k * 9 + j]; d += e * e; }
            if (d < bd) { bd = d; bk = k; }
        }
        for (int j = 0; j < 9; j++) g_qw2[t * 9 + j] = cdw2[bk * 9 + j];
    }
    for (int c = t; c < OC; c += 256) {
        float w = pw1[c]; float bd = 3.4e38f; int bk = 0;
        for (int k = 0; k < 256; k++) { float e = w - cpw[k]; float d = e * e; if (d < bd) { bd = d; bk = k; } }
        g_qpw1[c] = cpw[bk];
        w = pw2[c]; bd = 3.4e38f; bk = 0;
        for (int k = 0; k < 256; k++) { float e = w - cpw2[k]; float d = e * e; if (d < bd) { bd = d; bk = k; } }
        g_qpw2[c] = cpw2[bk];
    }
}

__device__ __forceinline__ float4 ld4_guard(const float* p, int k, int kend) {
    // k and kend are multiples of 4, so (k < kend) implies a full in-range float4
    return (k < kend) ? *(const float4*)(p + k) : make_float4(0.f, 0.f, 0.f, 0.f);
}

// ---------------- high-throughput SGEMM C = A (512xK) * B^T (512xK), split-K + z-batched ----
// grid: (4, 4, n_t * nsplit).  z -> t = z/nsplit (A batch), s = z%nsplit (K chunk).
// Partial result written to C + z*512*512.
__global__ void __launch_bounds__(256) sgemm_nt(
    const float* __restrict__ A, const float* __restrict__ B, float* __restrict__ C,
    int K, int Kchunk, int nsplit, long sAz)
{
    const int M = NF, N = NF;
    int z = blockIdx.z;
    int t = z / nsplit, s = z - t * nsplit;
    A += (long)t * sAz;
    C += (long)z * M * N;
    int kb = s * Kchunk;
    int kend = min(K, kb + Kchunk);

    __shared__ float As[2][8][128];
    __shared__ float Bs[2][8][128];

    int tid = threadIdx.x;
    int m0 = blockIdx.y * 128, n0 = blockIdx.x * 128;
    int lr = tid >> 1;           // 0..127
    int lc = (tid & 1) * 4;      // 0 or 4
    int tx = tid & 15, ty = tid >> 4;

    const float* Ab = A + (long)(m0 + lr) * K;
    const float* Bb = B + (long)(n0 + lr) * K;

    float acc[8][8] = {};

    float4 a4 = ld4_guard(Ab, kb + lc, kend);
    float4 b4 = ld4_guard(Bb, kb + lc, kend);
    As[0][lc + 0][lr] = a4.x; As[0][lc + 1][lr] = a4.y; As[0][lc + 2][lr] = a4.z; As[0][lc + 3][lr] = a4.w;
    Bs[0][lc + 0][lr] = b4.x; Bs[0][lc + 1][lr] = b4.y; Bs[0][lc + 2][lr] = b4.z; Bs[0][lc + 3][lr] = b4.w;
    __syncthreads();

    int buf = 0;
    for (int k0 = kb; k0 < kend; k0 += 8) {
        bool nxt = (k0 + 8) < kend;
        float4 na, nb;
        if (nxt) {
            na = ld4_guard(Ab, k0 + 8 + lc, kend);
            nb = ld4_guard(Bb, k0 + 8 + lc, kend);
        }
#pragma unroll
        for (int kk = 0; kk < 8; kk++) {
            float4 a0 = *(const float4*)&As[buf][kk][ty * 4];
            float4 a1 = *(const float4*)&As[buf][kk][64 + ty * 4];
            float4 b0 = *(const float4*)&Bs[buf][kk][tx * 4];
            float4 b1 = *(const float4*)&Bs[buf][kk][64 + tx * 4];
            float ar_[8] = { a0.x, a0.y, a0.z, a0.w, a1.x, a1.y, a1.z, a1.w };
            float br_[8] = { b0.x, b0.y, b0.z, b0.w, b1.x, b1.y, b1.z, b1.w };
#pragma unroll
            for (int i = 0; i < 8; i++)
#pragma unroll
                for (int j = 0; j < 8; j++) acc[i][j] += ar_[i] * br_[j];
        }
        if (nxt) {
            int bN = buf ^ 1;
            As[bN][lc + 0][lr] = na.x; As[bN][lc + 1][lr] = na.y; As[bN][lc + 2][lr] = na.z; As[bN][lc + 3][lr] = na.w;
            Bs[bN][lc + 0][lr] = nb.x; Bs[bN][lc + 1][lr] = nb.y; Bs[bN][lc + 2][lr] = nb.z; Bs[bN][lc + 3][lr] = nb.w;
            __syncthreads();
            buf = bN;
        }
    }

#pragma unroll
    for (int i = 0; i < 8; i++) {
        int m = m0 + (i < 4 ? ty * 4 + i : 64 + ty * 4 + i - 4);
        float* Cr = C + (long)m * N + n0;
        *(float4*)(Cr + tx * 4)      = make_float4(acc[i][0], acc[i][1], acc[i][2], acc[i][3]);
        *(float4*)(Cr + 64 + tx * 4) = make_float4(acc[i][4], acc[i][5], acc[i][6], acc[i][7]);
    }
}

// ---------------- output GEMM: C = A (512x512) * B (512xN), fused BN + LeakyReLU -------------
__global__ void __launch_bounds__(256) sgemm_nn_bn(
    const float* __restrict__ A, const float* __restrict__ B, float* __restrict__ C,
    int N, int K,
    const float* __restrict__ gamma, const float* __restrict__ beta,
    const float* __restrict__ rmean, const float* __restrict__ rvar)
{
    __shared__ float As[2][8][128];
    __shared__ float Bs[2][8][128];

    int tid = threadIdx.x;
    int m0 = blockIdx.y * 128, n0 = blockIdx.x * 128;
    int lr = tid >> 1, lc = (tid & 1) * 4;     // A loader
    int kb_ = tid >> 5, nb_ = (tid & 31) * 4;  // B loader
    int tx = tid & 15, ty = tid >> 4;

    const float* Ab = A + (long)(m0 + lr) * K;
    float acc[8][8] = {};

    float4 a4 = *(const float4*)(Ab + lc);
    As[0][lc + 0][lr] = a4.x; As[0][lc + 1][lr] = a4.y; As[0][lc + 2][lr] = a4.z; As[0][lc + 3][lr] = a4.w;
    float4 b4 = (n0 + nb_ < N) ? *(const float4*)(B + (long)kb_ * N + n0 + nb_)
                               : make_float4(0.f, 0.f, 0.f, 0.f);
    *(float4*)&Bs[0][kb_][nb_] = b4;
    __syncthreads();

    int buf = 0;
    for (int k0 = 0; k0 < K; k0 += 8) {
        bool nxt = (k0 + 8) < K;
        float4 na, nb;
        if (nxt) {
            na = *(const float4*)(Ab + k0 + 8 + lc);
            nb = (n0 + nb_ < N) ? *(const float4*)(B + (long)(k0 + 8 + kb_) * N + n0 + nb_)
                                : make_float4(0.f, 0.f, 0.f, 0.f);
        }
#pragma unroll
        for (int kk = 0; kk < 8; kk++) {
            float4 a0 = *(const float4*)&As[buf][kk][ty * 4];
            float4 a1 = *(const float4*)&As[buf][kk][64 + ty * 4];
            float4 b0 = *(const float4*)&Bs[buf][kk][tx * 4];
            float4 b1 = *(const float4*)&Bs[buf][kk][64 + tx * 4];
            float ar_[8] = { a0.x, a0.y, a0.z, a0.w, a1.x, a1.y, a1.z, a1.w };
            float br_[8] = { b0.x, b0.y, b0.z, b0.w, b1.x, b1.y, b1.z, b1.w };
#pragma unroll
            for (int i = 0; i < 8; i++)
#pragma unroll
                for (int j = 0; j < 8; j++) acc[i][j] += ar_[i] * br_[j];
        }
        if (nxt) {
            int bN = buf ^ 1;
            As[bN][lc + 0][lr] = na.x; As[bN][lc + 1][lr] = na.y; As[bN][lc + 2][lr] = na.z; As[bN][lc + 3][lr] = na.w;
            *(float4*)&Bs[bN][kb_][nb_] = nb;
            __syncthreads();
            buf = bN;
        }
    }

#pragma unroll
    for (int i = 0; i < 8; i++) {
        int m = m0 + (i < 4 ? ty * 4 + i : 64 + ty * 4 + i - 4);
        int g = m & 31;
        float sc = rsqrtf(rvar[g] + BN_EPS) * gamma[g];
        float mu = rmean[g], bt = beta[g];
#pragma unroll
        for (int j = 0; j < 8; j++) {
            int n = n0 + (j < 4 ? tx * 4 + j : 64 + tx * 4 + j - 4);
            if (n < N) {
                float v = (acc[i][j] - mu) * sc + bt;
                C[(long)m * N + n] = (v >= 0.f) ? v : LEAK * v;
            }
        }
    }
}

// ---------------- row-wise argmin of (norms[k] - 2*sum_s Sp[s,row,k]) ----------------
__global__ void argmin_rows(const float* __restrict__ Sp, const float* __restrict__ norms,
                            int* __restrict__ out, int nsplit) {
    int row = blockIdx.x;
    float bd = 3.4e38f; int bk = 0;
    for (int k = threadIdx.x; k < NF; k += 256) {
        float s = 0.f;
        for (int sp = 0; sp < nsplit; sp++)
            s += Sp[((long)sp * NF + row) * NF + k];
        float d = norms[k] - 2.0f * s;
        if (d < bd) { bd = d; bk = k; }
    }
    __shared__ float sd[256]; __shared__ int si[256];
    sd[threadIdx.x] = bd; si[threadIdx.x] = bk; __syncthreads();
    for (int o = 128; o > 0; o >>= 1) {
        if (threadIdx.x < o) {
            float d2 = sd[threadIdx.x + o]; int k2 = si[threadIdx.x + o];
            if (d2 < sd[threadIdx.x] || (d2 == sd[threadIdx.x] && k2 < si[threadIdx.x])) {
                sd[threadIdx.x] = d2; si[threadIdx.x] = k2;
            }
        }
        __syncthreads();
    }
    if (threadIdx.x == 0) out[row] = si[0];
}

// ---------------- conv1: h1[v] = lrelu(conv3x3(cb_fdw[idx0[v]], qw1[v%32])) ----------------
__global__ void conv1_lrelu(const float* __restrict__ cb_fdw) {
    int v = blockIdx.x;
    int i = v & 31;
    __shared__ float w[9];
    if (threadIdx.x < 9) w[threadIdx.x] = g_qw1[i * 9 + threadIdx.x];
    __syncthreads();
    const float* src = cb_fdw + (long)g_idx0[v] * D0;
    for (int p = threadIdx.x; p < D1; p += 256) {
        int py = p / H2c, px = p - py * H2c;
        const float* s0 = src + py * H0c + px;
        float acc = s0[0] * w[0] + s0[1] * w[1] + s0[2] * w[2]
                  + s0[H0c] * w[3] + s0[H0c + 1] * w[4] + s0[H0c + 2] * w[5]
                  + s0[2 * H0c] * w[6] + s0[2 * H0c + 1] * w[7] + s0[2 * H0c + 2] * w[8];
        g_h1[(long)v * D1 + p] = (acc >= 0.f) ? acc : LEAK * acc;
    }
}

// ---------------- idx2: argmin_k (||c_k||^2 - 2 s DOT1[j,k]) for 16384 (b,c') rows ----------
__global__ void idx2_kernel(int nsplit) {
    int vbi = blockIdx.x;           // b*32 + i
    int b = vbi >> 5, i = vbi & 31;
    int j = g_idx1[vbi];
    __shared__ float dr[NF]; __shared__ float nn[NF];
    for (int k = threadIdx.x; k < NF; k += 256) {
        float v = 0.f;
        for (int sp = 0; sp < nsplit; sp++)
            v += g_Sp[((long)sp * NF + j) * NF + k];
        dr[k] = v;
        nn[k] = g_nfdw2[k];
    }
    __syncthreads();
    if (threadIdx.x < 32) {
        int o = threadIdx.x;
        float s = g_qpw1[o * 32 + i];
        float bd = 3.4e38f; int bk = 0;
        for (int k = 0; k < NF; k++) {
            float d = nn[k] - 2.0f * s * dr[k];
            if (d < bd) { bd = d; bk = k; }
        }
        g_idx2[b * OC + o * 32 + i] = bk;
    }
}

// ---------------- shifted copies of cb_fdw2 for the G GEMMs ----------------
__global__ void shift_prep(const float* __restrict__ cb_fdw2) {
    int k = blockIdx.x, t = blockIdx.y;
    int ty = t / 3, tx = t - ty * 3;
    const float* src = cb_fdw2 + (long)k * D1;
    float* dst = g_Cs + ((long)t * NF + k) * D2;
    for (int p = threadIdx.x; p < D2; p += 256) {
        int py = p / H3c, px = p - py * H3c;
        dst[p] = src[(py + ty) * H2c + px + tx];
    }
}

// ---------------- pair: for each k, all-o argmin_m(||P_m||^2 - 2 sum_t w_o[t] G[t,k,m]) -----
__global__ void __launch_bounds__(256) pair_kernel(int nsplit) {
    int k = blockIdx.x;
    __shared__ float gs[9][NF];
    __shared__ float nn[NF];
    __shared__ float ws[CH * 9];
    for (int t = 0; t < 9; t++)
        for (int m = threadIdx.x; m < NF; m += 256) {
            float v = 0.f;
            for (int s = 0; s < nsplit; s++)
                v += g_Gp[((long)(t * nsplit + s) * NF + k) * NF + m];
            gs[t][m] = v;
        }
    for (int i = threadIdx.x; i < CH * 9; i += 256) ws[i] = g_qw2[i];
    for (int m = threadIdx.x; m < NF; m += 256) nn[m] = g_nfpw2[m];
    __syncthreads();
    int warp = threadIdx.x >> 5, lane = threadIdx.x & 31;
    for (int o = warp; o < CH; o += 8) {
        float wv[9];
#pragma unroll
        for (int t = 0; t < 9; t++) wv[t] = ws[o * 9 + t];
        float bd = 3.4e38f; int bk = 0;
        for (int m = lane; m < NF; m += 32) {
            float T = 0.f;
#pragma unroll
            for (int t = 0; t < 9; t++) T += wv[t] * gs[t][m];
            float d = nn[m] - 2.0f * T;
            if (d < bd) { bd = d; bk = m; }
        }
        for (int off = 16; off > 0; off >>= 1) {
            float d2 = __shfl_down_sync(0xffffffffu, bd, off);
            int k2 = __shfl_down_sync(0xffffffffu, bk, off);
            if (d2 < bd || (d2 == bd && k2 < bk)) { bd = d2; bk = k2; }
        }
        if (lane == 0) g_pair[k * CH + o] = bk;
    }
}

// ---------------- histogram of idx3 per (b,o) (deterministic, serial per block) -------------
__global__ void cnt_kernel() {
    int bo = blockIdx.x;  // b*32+o
    __shared__ int c[NF];
    for (int m = threadIdx.x; m < NF; m += 256) c[m] = 0;
    __syncthreads();
    if (threadIdx.x == 0) {
        int b = bo >> 5, o = bo & 31;
        for (int i = 0; i < 32; i++) {
            int k2 = g_idx2[b * OC + o * 32 + i];
            c[g_pair[k2 * CH + o]]++;
        }
    }
    __syncthreads();
    for (int m = threadIdx.x; m < NF; m += 256) g_cnt[(long)bo * NF + m] = c[m];
}

// ---------------- A[bg][m] = sum_o qpw2[g*32+o] * cnt[b][o][m] ----------------
__global__ void A_kernel() {
    int bg = blockIdx.x;
    int b = bg >> 5, g = bg & 31;
    __shared__ float w[32];
    if (threadIdx.x < 32) w[threadIdx.x] = g_qpw2[g * 32 + threadIdx.x];
    __syncthreads();
    for (int m = threadIdx.x; m < NF; m += 256) {
        float acc = 0.f;
#pragma unroll
        for (int o = 0; o < 32; o++)
            acc += w[o] * (float)g_cnt[((long)(b * 32 + o)) * NF + m];
        g_A[(long)bg * NF + m] = acc;
    }
}

extern "C" void kernel_launch(void* const* d_in, const int* in_sizes, int n_in,
                              void* d_out, int out_size) {
    const float* x       = (const float*)d_in[0];
    const float* dw_w1   = (const float*)d_in[1];
    const float* pw_w1   = (const float*)d_in[2];
    const float* dw_w2   = (const float*)d_in[3];
    const float* pw_w2   = (const float*)d_in[4];
    const float* cb_dw   = (const float*)d_in[5];
    const float* cb_pw   = (const float*)d_in[6];
    const float* cb_dw2  = (const float*)d_in[7];
    const float* cb_pw2  = (const float*)d_in[8];
    const float* cb_fdw  = (const float*)d_in[9];
    const float* cb_fpw  = (const float*)d_in[10];
    const float* cb_fdw2 = (const float*)d_in[11];
    const float* cb_fpw2 = (const float*)d_in[12];
    const float* gamma   = (const float*)d_in[13];
    const float* beta    = (const float*)d_in[14];
    const float* rmean   = (const float*)d_in[15];
    const float* rvar    = (const float*)d_in[16];
    float* out = (float*)d_out;

    float *pSp, *pGp, *ph1, *pCs, *pA;
    cudaGetSymbolAddress((void**)&pSp, g_Sp);
    cudaGetSymbolAddress((void**)&pGp, g_Gp);
    cudaGetSymbolAddress((void**)&ph1, g_h1);
    cudaGetSymbolAddress((void**)&pCs, g_Cs);
    cudaGetSymbolAddress((void**)&pA, g_A);
    int *pidx0, *pidx1;
    cudaGetSymbolAddress((void**)&pidx0, g_idx0);
    cudaGetSymbolAddress((void**)&pidx1, g_idx1);
    float *pnfdw, *pnfpw;
    cudaGetSymbolAddress((void**)&pnfdw, g_nfdw);
    cudaGetSymbolAddress((void**)&pnfpw, g_nfpw);

    // norms + weight VQ
    norms_kernel<<<dim3(NF, 4), 256>>>(cb_fdw, cb_fpw, cb_fdw2, cb_fpw2);
    quantw_kernel<<<1, 256>>>(dw_w1, pw_w1, dw_w2, pw_w2, cb_dw, cb_pw, cb_dw2, cb_pw2);

    // stage A: VQ0  (K=2304, split 8 x 288)
    sgemm_nt<<<dim3(4, 4, 8), 256>>>(x, cb_fdw, pSp, D0, 288, 8, 0);
    argmin_rows<<<BI, 256>>>(pSp, pnfdw, pidx0, 8);

    // stage B: dwconv1 + lrelu
    conv1_lrelu<<<BI, 256>>>(cb_fdw);

    // stage C: VQ1  (K=2116, split 8 x 272)
    sgemm_nt<<<dim3(4, 4, 8), 256>>>(ph1, cb_fpw, pSp, D1, 272, 8, 0);
    argmin_rows<<<BI, 256>>>(pSp, pnfpw, pidx1, 8);

    // stage E: DOT1 = cb_fpw . cb_fdw2^T, then idx2 table scan
    sgemm_nt<<<dim3(4, 4, 8), 256>>>(cb_fpw, cb_fdw2, pSp, D1, 272, 8, 0);
    idx2_kernel<<<BI, 256>>>(8);

    // stage F: G (9 shifted GEMMs, split-K 2) -> per-k pair argmin
    shift_prep<<<dim3(NF, 9), 256>>>(cb_fdw2);
    sgemm_nt<<<dim3(4, 4, 18), 256>>>(pCs, cb_fpw2, pGp, D2, 968, 2, (long)NF * D2);
    pair_kernel<<<NF, 256>>>(2);

    // stage G: histogram -> A -> output GEMM with fused BN + lrelu
    cnt_kernel<<<B_ * CH, 256>>>();
    A_kernel<<<BI, 256>>>();
    sgemm_nn_bn<<<dim3(16, 4), 256>>>(pA, cb_fpw2, out, D2, NF,
                                      gamma, beta, rmean, rvar);
}

// round 4
// speedup vs baseline: 1.7586x; 1.0562x over previous
#include <cuda_runtime.h>

#define LEAK   0.1f
#define BN_EPS 1e-5f

// problem dims
#define B_   16
#define CH   32
#define H0c  48
#define H2c  46
#define H3c  44
#define D0   2304
#define D1   2116
#define D2   1936
#define NF   512
#define BI   512
#define OC   1024
#define BOC  16384
#define NN2  (NF * NF)
#define OSL  (512 * D2)          // out-partial slice stride

// ---------------- scratch ----------------
__device__ float g_Sp[8 * NN2];         // VQ0 partials [0:4), DOT1 partials [4:8)
__device__ float g_Gp[27 * NN2];        // G partials (t*3+s); later reused for VQ1 (8 slices)
__device__ float g_h1[BI * D1];
__device__ float g_Cs[9 * NF * D2];     // shifted cb_fdw2; later reused for out partials (2 slices)
__device__ float g_A[BI * NF];
__device__ int   g_cnt[B_ * CH * NF];
__device__ int   g_idx0[BI];
__device__ int   g_idx1[BI];
__device__ int   g_idx2[BOC];
__device__ int   g_pair[NF * CH];
__device__ float g_qw1[CH * 9];
__device__ float g_qw2[CH * 9];
__device__ float g_qpw1[OC];
__device__ float g_qpw2[OC];
__device__ float g_nfdw[NF];
__device__ float g_nfpw[NF];
__device__ float g_nfdw2[NF];
__device__ float g_nfpw2[NF];

// ---------------- packed fp32x2 helpers ----------------
#define PACK2(d, x, y) asm("mov.b64 %0, {%1, %2};" : "=l"(d) : "r"(__float_as_uint(x)), "r"(__float_as_uint(y)))
#define FMA2(acc, a, b) asm("fma.rn.f32x2 %0, %1, %2, %0;" : "+l"(acc) : "l"(a), "l"(b))
__device__ __forceinline__ void unpk2(unsigned long long v, float& lo, float& hi) {
    unsigned int l, h;
    asm("mov.b64 {%0, %1}, %2;" : "=r"(l), "=r"(h) : "l"(v));
    lo = __uint_as_float(l); hi = __uint_as_float(h);
}

// ---------------- codebook row norms ----------------
__global__ void norms_kernel(const float* __restrict__ fdw, const float* __restrict__ fpw,
                             const float* __restrict__ fdw2, const float* __restrict__ fpw2) {
    int row = blockIdx.x;
    int which = blockIdx.y;
    const float* src; int D; float* dst;
    if (which == 0)      { src = fdw;  D = D0; dst = g_nfdw;  }
    else if (which == 1) { src = fpw;  D = D1; dst = g_nfpw;  }
    else if (which == 2) { src = fdw2; D = D1; dst = g_nfdw2; }
    else                 { src = fpw2; D = D2; dst = g_nfpw2; }
    const float* p = src + (long)row * D;
    float s = 0.f;
    for (int i = threadIdx.x; i < D; i += 256) { float v = p[i]; s += v * v; }
    __shared__ float sm[256];
    sm[threadIdx.x] = s; __syncthreads();
    for (int o = 128; o > 0; o >>= 1) {
        if (threadIdx.x < o) sm[threadIdx.x] += sm[threadIdx.x + o];
        __syncthreads();
    }
    if (threadIdx.x == 0) dst[row] = sm[0];
}

// ---------------- weight VQ (tiny) ----------------
__global__ void quantw_kernel(const float* __restrict__ dw1, const float* __restrict__ pw1,
                              const float* __restrict__ dw2, const float* __restrict__ pw2,
                              const float* __restrict__ cdw, const float* __restrict__ cpw,
                              const float* __restrict__ cdw2, const float* __restrict__ cpw2) {
    int t = threadIdx.x;
    if (t < 32) {
        float w[9];
        for (int j = 0; j < 9; j++) w[j] = dw1[t * 9 + j];
        float bd = 3.4e38f; int bk = 0;
        for (int k = 0; k < 256; k++) {
            float d = 0.f;
            for (int j = 0; j < 9; j++) { float e = w[j] - cdw[k * 9 + j]; d += e * e; }
            if (d < bd) { bd = d; bk = k; }
        }
        for (int j = 0; j < 9; j++) g_qw1[t * 9 + j] = cdw[bk * 9 + j];
        for (int j = 0; j < 9; j++) w[j] = dw2[t * 9 + j];
        bd = 3.4e38f; bk = 0;
        for (int k = 0; k < 256; k++) {
            float d = 0.f;
            for (int j = 0; j < 9; j++) { float e = w[j] - cdw2[k * 9 + j]; d += e * e; }
            if (d < bd) { bd = d; bk = k; }
        }
        for (int j = 0; j < 9; j++) g_qw2[t * 9 + j] = cdw2[bk * 9 + j];
    }
    for (int c = t; c < OC; c += 256) {
        float w = pw1[c]; float bd = 3.4e38f; int bk = 0;
        for (int k = 0; k < 256; k++) { float e = w - cpw[k]; float d = e * e; if (d < bd) { bd = d; bk = k; } }
        g_qpw1[c] = cpw[bk];
        w = pw2[c]; bd = 3.4e38f; bk = 0;
        for (int k = 0; k < 256; k++) { float e = w - cpw2[k]; float d = e * e; if (d < bd) { bd = d; bk = k; } }
        g_qpw2[c] = cpw2[bk];
    }
}

__device__ __forceinline__ float4 ld4_guard(const float* p, int k, int kend) {
    return (k < kend) ? *(const float4*)(p + k) : make_float4(0.f, 0.f, 0.f, 0.f);
}

// ---------------- NT GEMM core: C[512x512] (+ tile offsets) = A*B^T over K chunk [kb,kend) ----
__device__ __forceinline__ void nt_core(const float* __restrict__ A, const float* __restrict__ B,
                                        float* __restrict__ C, int ldk, int kb, int kend) {
    __shared__ float As[2][8][128];
    __shared__ float Bs[2][8][128];
    int tid = threadIdx.x;
    int m0 = blockIdx.y * 128, n0 = blockIdx.x * 128;
    int lr = tid >> 1, lc = (tid & 1) * 4;
    int tx = tid & 15, ty = tid >> 4;

    const float* Ab = A + (long)(m0 + lr) * ldk;
    const float* Bb = B + (long)(n0 + lr) * ldk;

    unsigned long long acc[8][4] = {};

    float4 a4 = ld4_guard(Ab, kb + lc, kend);
    float4 b4 = ld4_guard(Bb, kb + lc, kend);
    As[0][lc + 0][lr] = a4.x; As[0][lc + 1][lr] = a4.y; As[0][lc + 2][lr] = a4.z; As[0][lc + 3][lr] = a4.w;
    Bs[0][lc + 0][lr] = b4.x; Bs[0][lc + 1][lr] = b4.y; Bs[0][lc + 2][lr] = b4.z; Bs[0][lc + 3][lr] = b4.w;
    __syncthreads();

    int buf = 0;
    for (int k0 = kb; k0 < kend; k0 += 8) {
        bool nxt = (k0 + 8) < kend;
        float4 na, nb;
        if (nxt) {
            na = ld4_guard(Ab, k0 + 8 + lc, kend);
            nb = ld4_guard(Bb, k0 + 8 + lc, kend);
        }
#pragma unroll
        for (int kk = 0; kk < 8; kk++) {
            float4 a0 = *(const float4*)&As[buf][kk][ty * 4];
            float4 a1 = *(const float4*)&As[buf][kk][64 + ty * 4];
            float4 b0 = *(const float4*)&Bs[buf][kk][tx * 4];
            float4 b1 = *(const float4*)&Bs[buf][kk][64 + tx * 4];
            unsigned long long bp0, bp1, bp2, bp3;
            PACK2(bp0, b0.x, b0.y); PACK2(bp1, b0.z, b0.w);
            PACK2(bp2, b1.x, b1.y); PACK2(bp3, b1.z, b1.w);
            float ar[8] = { a0.x, a0.y, a0.z, a0.w, a1.x, a1.y, a1.z, a1.w };
#pragma unroll
            for (int i = 0; i < 8; i++) {
                unsigned long long ap; PACK2(ap, ar[i], ar[i]);
                FMA2(acc[i][0], ap, bp0); FMA2(acc[i][1], ap, bp1);
                FMA2(acc[i][2], ap, bp2); FMA2(acc[i][3], ap, bp3);
            }
        }
        if (nxt) {
            int bN = buf ^ 1;
            As[bN][lc + 0][lr] = na.x; As[bN][lc + 1][lr] = na.y; As[bN][lc + 2][lr] = na.z; As[bN][lc + 3][lr] = na.w;
            Bs[bN][lc + 0][lr] = nb.x; Bs[bN][lc + 1][lr] = nb.y; Bs[bN][lc + 2][lr] = nb.z; Bs[bN][lc + 3][lr] = nb.w;
            __syncthreads();
            buf = bN;
        }
    }

#pragma unroll
    for (int i = 0; i < 8; i++) {
        int m = m0 + (i < 4 ? ty * 4 + i : 64 + ty * 4 + i - 4);
        float* Cr = C + (long)m * NF + n0;
        *(unsigned long long*)(Cr + tx * 4)          = acc[i][0];
        *(unsigned long long*)(Cr + tx * 4 + 2)      = acc[i][1];
        *(unsigned long long*)(Cr + 64 + tx * 4)     = acc[i][2];
        *(unsigned long long*)(Cr + 64 + tx * 4 + 2) = acc[i][3];
    }
}

// ---------------- mega-batched NT GEMM: VQ0 (4 splits) + DOT1 (4 splits) + G (9x3 splits) ----
__global__ void __launch_bounds__(256) mega_gemm(
    const float* __restrict__ x, const float* __restrict__ cbfdw,
    const float* __restrict__ cbfpw, const float* __restrict__ cbfdw2,
    const float* __restrict__ Cs, const float* __restrict__ cbfpw2,
    float* __restrict__ Sp, float* __restrict__ Gp)
{
    int z = blockIdx.z;
    const float* A; const float* B; float* C; int K, kb, kend;
    if (z < 4) {
        A = x; B = cbfdw; K = D0; kb = z * 576; kend = kb + 576; C = Sp + (long)z * NN2;
    } else if (z < 8) {
        int s = z - 4;
        A = cbfpw; B = cbfdw2; K = D1; kb = s * 532; kend = min(D1, kb + 532); C = Sp + (long)z * NN2;
    } else {
        int zz = z - 8, t = zz / 3, s = zz - t * 3;
        A = Cs + (long)t * NF * D2; B = cbfpw2; K = D2;
        kb = s * 648; kend = min(D2, kb + 648); C = Gp + (long)zz * NN2;
    }
    nt_core(A, B, C, K, kb, kend);
}

// ---------------- standalone NT GEMM (VQ1), split-K over z ----------------
__global__ void __launch_bounds__(256) sgemm_nt(
    const float* __restrict__ A, const float* __restrict__ B, float* __restrict__ C,
    int K, int Kchunk)
{
    int s = blockIdx.z;
    int kb = s * Kchunk;
    int kend = min(K, kb + Kchunk);
    nt_core(A, B, C + (long)s * NN2, K, kb, kend);
}

// ---------------- out GEMM: partial C = A (512x512 chunk) * B (512x1936), split-K 2 ----------
__global__ void __launch_bounds__(256) sgemm_nn_split(
    const float* __restrict__ A, const float* __restrict__ B, float* __restrict__ C)
{
    const int N = D2, K = NF;
    int kb = blockIdx.z * 256, kend = kb + 256;
    C += (long)blockIdx.z * OSL;

    __shared__ float As[2][8][128];
    __shared__ float Bs[2][8][128];

    int tid = threadIdx.x;
    int m0 = blockIdx.y * 128, n0 = blockIdx.x * 128;
    int lr = tid >> 1, lc = (tid & 1) * 4;
    int kb_ = tid >> 5, nb_ = (tid & 31) * 4;
    int tx = tid & 15, ty = tid >> 4;

    const float* Ab = A + (long)(m0 + lr) * K;
    unsigned long long acc[8][4] = {};

    float4 a4 = *(const float4*)(Ab + kb + lc);
    As[0][lc + 0][lr] = a4.x; As[0][lc + 1][lr] = a4.y; As[0][lc + 2][lr] = a4.z; As[0][lc + 3][lr] = a4.w;
    float4 b4 = (n0 + nb_ < N) ? *(const float4*)(B + (long)(kb + kb_) * N + n0 + nb_)
                               : make_float4(0.f, 0.f, 0.f, 0.f);
    *(float4*)&Bs[0][kb_][nb_] = b4;
    __syncthreads();

    int buf = 0;
    for (int k0 = kb; k0 < kend; k0 += 8) {
        bool nxt = (k0 + 8) < kend;
        float4 na, nb;
        if (nxt) {
            na = *(const float4*)(Ab + k0 + 8 + lc);
            nb = (n0 + nb_ < N) ? *(const float4*)(B + (long)(k0 + 8 + kb_) * N + n0 + nb_)
                                : make_float4(0.f, 0.f, 0.f, 0.f);
        }
#pragma unroll
        for (int kk = 0; kk < 8; kk++) {
            float4 a0 = *(const float4*)&As[buf][kk][ty * 4];
            float4 a1 = *(const float4*)&As[buf][kk][64 + ty * 4];
            float4 b0 = *(const float4*)&Bs[buf][kk][tx * 4];
            float4 b1 = *(const float4*)&Bs[buf][kk][64 + tx * 4];
            unsigned long long bp0, bp1, bp2, bp3;
            PACK2(bp0, b0.x, b0.y); PACK2(bp1, b0.z, b0.w);
            PACK2(bp2, b1.x, b1.y); PACK2(bp3, b1.z, b1.w);
            float ar[8] = { a0.x, a0.y, a0.z, a0.w, a1.x, a1.y, a1.z, a1.w };
#pragma unroll
            for (int i = 0; i < 8; i++) {
                unsigned long long ap; PACK2(ap, ar[i], ar[i]);
                FMA2(acc[i][0], ap, bp0); FMA2(acc[i][1], ap, bp1);
                FMA2(acc[i][2], ap, bp2); FMA2(acc[i][3], ap, bp3);
            }
        }
        if (nxt) {
            int bN = buf ^ 1;
            As[bN][lc + 0][lr] = na.x; As[bN][lc + 1][lr] = na.y; As[bN][lc + 2][lr] = na.z; As[bN][lc + 3][lr] = na.w;
            *(float4*)&Bs[bN][kb_][nb_] = nb;
            __syncthreads();
            buf = bN;
        }
    }

#pragma unroll
    for (int i = 0; i < 8; i++) {
        int m = m0 + (i < 4 ? ty * 4 + i : 64 + ty * 4 + i - 4);
        float* Cr = C + (long)m * N;
#pragma unroll
        for (int jp = 0; jp < 4; jp++) {
            float lo, hi; unpk2(acc[i][jp], lo, hi);
            int n = n0 + (jp < 2 ? tx * 4 + jp * 2 : 64 + tx * 4 + (jp - 2) * 2);
            if (n < N)     Cr[n] = lo;
            if (n + 1 < N) Cr[n + 1] = hi;
        }
    }
}

// ---------------- BN + lrelu reduce of 2 out partials ----------------
__global__ void bn_reduce(const float* __restrict__ P, float* __restrict__ out,
                          const float* __restrict__ gamma, const float* __restrict__ beta,
                          const float* __restrict__ rmean, const float* __restrict__ rvar) {
    int m = blockIdx.x;
    int g = m & 31;
    float sc = rsqrtf(rvar[g] + BN_EPS) * gamma[g];
    float mu = rmean[g], bt = beta[g];
    const float* p0 = P + (long)m * D2;
    const float* p1 = p0 + OSL;
    float* o = out + (long)m * D2;
    for (int n = threadIdx.x; n < D2; n += 256) {
        float v = (p0[n] + p1[n] - mu) * sc + bt;
        o[n] = (v >= 0.f) ? v : LEAK * v;
    }
}

// ---------------- row-wise argmin of (norms[k] - 2*sum_s Sp[s,row,k]) ----------------
__global__ void argmin_rows(const float* __restrict__ Sp, const float* __restrict__ norms,
                            int* __restrict__ out, int nsplit) {
    int row = blockIdx.x;
    float bd = 3.4e38f; int bk = 0;
    for (int k = threadIdx.x; k < NF; k += 256) {
        float s = 0.f;
        for (int sp = 0; sp < nsplit; sp++)
            s += Sp[((long)sp * NF + row) * NF + k];
        float d = norms[k] - 2.0f * s;
        if (d < bd) { bd = d; bk = k; }
    }
    __shared__ float sd[256]; __shared__ int si[256];
    sd[threadIdx.x] = bd; si[threadIdx.x] = bk; __syncthreads();
    for (int o = 128; o > 0; o >>= 1) {
        if (threadIdx.x < o) {
            float d2 = sd[threadIdx.x + o]; int k2 = si[threadIdx.x + o];
            if (d2 < sd[threadIdx.x] || (d2 == sd[threadIdx.x] && k2 < si[threadIdx.x])) {
                sd[threadIdx.x] = d2; si[threadIdx.x] = k2;
            }
        }
        __syncthreads();
    }
    if (threadIdx.x == 0) out[row] = si[0];
}

// ---------------- conv1 + lrelu ----------------
__global__ void conv1_lrelu(const float* __restrict__ cb_fdw) {
    int v = blockIdx.x;
    int i = v & 31;
    __shared__ float w[9];
    if (threadIdx.x < 9) w[threadIdx.x] = g_qw1[i * 9 + threadIdx.x];
    __syncthreads();
    const float* src = cb_fdw + (long)g_idx0[v] * D0;
    for (int p = threadIdx.x; p < D1; p += 256) {
        int py = p / H2c, px = p - py * H2c;
        const float* s0 = src + py * H0c + px;
        float acc = s0[0] * w[0] + s0[1] * w[1] + s0[2] * w[2]
                  + s0[H0c] * w[3] + s0[H0c + 1] * w[4] + s0[H0c + 2] * w[5]
                  + s0[2 * H0c] * w[6] + s0[2 * H0c + 1] * w[7] + s0[2 * H0c + 2] * w[8];
        g_h1[(long)v * D1 + p] = (acc >= 0.f) ? acc : LEAK * acc;
    }
}

// ---------------- idx2: all 8 warps, each warp handles 4 o-values ----------------
__global__ void idx2_kernel(const float* __restrict__ DOT, int nsplit) {
    int vbi = blockIdx.x;           // b*32 + i
    int b = vbi >> 5, i = vbi & 31;
    int j = g_idx1[vbi];
    __shared__ float dr[NF]; __shared__ float nn[NF];
    for (int k = threadIdx.x; k < NF; k += 256) {
        float v = 0.f;
        for (int sp = 0; sp < nsplit; sp++)
            v += DOT[((long)sp * NF + j) * NF + k];
        dr[k] = v;
        nn[k] = g_nfdw2[k];
    }
    __syncthreads();
    int warp = threadIdx.x >> 5, lane = threadIdx.x & 31;
    for (int o = warp; o < CH; o += 8) {
        float s = g_qpw1[o * 32 + i];
        float bd = 3.4e38f; int bk = 0;
        for (int k = lane; k < NF; k += 32) {
            float d = nn[k] - 2.0f * s * dr[k];
            if (d < bd) { bd = d; bk = k; }
        }
        for (int off = 16; off > 0; off >>= 1) {
            float d2 = __shfl_down_sync(0xffffffffu, bd, off);
            int k2 = __shfl_down_sync(0xffffffffu, bk, off);
            if (d2 < bd || (d2 == bd && k2 < bk)) { bd = d2; bk = k2; }
        }
        if (lane == 0) g_idx2[b * OC + o * 32 + i] = bk;
    }
}

// ---------------- shifted copies of cb_fdw2 ----------------
__global__ void shift_prep(const float* __restrict__ cb_fdw2) {
    int k = blockIdx.x, t = blockIdx.y;
    int ty = t / 3, tx = t - ty * 3;
    const float* src = cb_fdw2 + (long)k * D1;
    float* dst = g_Cs + ((long)t * NF + k) * D2;
    for (int p = threadIdx.x; p < D2; p += 256) {
        int py = p / H3c, px = p - py * H3c;
        dst[p] = src[(py + ty) * H2c + px + tx];
    }
}

// ---------------- pair argmin over m per (k,o) ----------------
__global__ void __launch_bounds__(256) pair_kernel(int nsplit) {
    int k = blockIdx.x;
    __shared__ float gs[9][NF];
    __shared__ float nn[NF];
    __shared__ float ws[CH * 9];
    for (int t = 0; t < 9; t++)
        for (int m = threadIdx.x; m < NF; m += 256) {
            float v = 0.f;
            for (int s = 0; s < nsplit; s++)
                v += g_Gp[((long)(t * nsplit + s) * NF + k) * NF + m];
            gs[t][m] = v;
        }
    for (int i = threadIdx.x; i < CH * 9; i += 256) ws[i] = g_qw2[i];
    for (int m = threadIdx.x; m < NF; m += 256) nn[m] = g_nfpw2[m];
    __syncthreads();
    int warp = threadIdx.x >> 5, lane = threadIdx.x & 31;
    for (int o = warp; o < CH; o += 8) {
        float wv[9];
#pragma unroll
        for (int t = 0; t < 9; t++) wv[t] = ws[o * 9 + t];
        float bd = 3.4e38f; int bk = 0;
        for (int m = lane; m < NF; m += 32) {
            float T = 0.f;
#pragma unroll
            for (int t = 0; t < 9; t++) T += wv[t] * gs[t][m];
            float d = nn[m] - 2.0f * T;
            if (d < bd) { bd = d; bk = m; }
        }
        for (int off = 16; off > 0; off >>= 1) {
            float d2 = __shfl_down_sync(0xffffffffu, bd, off);
            int k2 = __shfl_down_sync(0xffffffffu, bk, off);
            if (d2 < bd || (d2 == bd && k2 < bk)) { bd = d2; bk = k2; }
        }
        if (lane == 0) g_pair[k * CH + o] = bk;
    }
}

// ---------------- histogram ----------------
__global__ void cnt_kernel() {
    int bo = blockIdx.x;
    __shared__ int c[NF];
    for (int m = threadIdx.x; m < NF; m += 256) c[m] = 0;
    __syncthreads();
    if (threadIdx.x == 0) {
        int b = bo >> 5, o = bo & 31;
        for (int i = 0; i < 32; i++) {
            int k2 = g_idx2[b * OC + o * 32 + i];
            c[g_pair[k2 * CH + o]]++;
        }
    }
    __syncthreads();
    for (int m = threadIdx.x; m < NF; m += 256) g_cnt[(long)bo * NF + m] = c[m];
}

// ---------------- A[bg][m] = sum_o qpw2[g*32+o] * cnt[b][o][m] ----------------
__global__ void A_kernel() {
    int bg = blockIdx.x;
    int b = bg >> 5, g = bg & 31;
    __shared__ float w[32];
    if (threadIdx.x < 32) w[threadIdx.x] = g_qpw2[g * 32 + threadIdx.x];
    __syncthreads();
    for (int m = threadIdx.x; m < NF; m += 256) {
        float acc = 0.f;
#pragma unroll
        for (int o = 0; o < 32; o++)
            acc += w[o] * (float)g_cnt[((long)(b * 32 + o)) * NF + m];
        g_A[(long)bg * NF + m] = acc;
    }
}

extern "C" void kernel_launch(void* const* d_in, const int* in_sizes, int n_in,
                              void* d_out, int out_size) {
    const float* x       = (const float*)d_in[0];
    const float* dw_w1   = (const float*)d_in[1];
    const float* pw_w1   = (const float*)d_in[2];
    const float* dw_w2   = (const float*)d_in[3];
    const float* pw_w2   = (const float*)d_in[4];
    const float* cb_dw   = (const float*)d_in[5];
    const float* cb_pw   = (const float*)d_in[6];
    const float* cb_dw2  = (const float*)d_in[7];
    const float* cb_pw2  = (const float*)d_in[8];
    const float* cb_fdw  = (const float*)d_in[9];
    const float* cb_fpw  = (const float*)d_in[10];
    const float* cb_fdw2 = (const float*)d_in[11];
    const float* cb_fpw2 = (const float*)d_in[12];
    const float* gamma   = (const float*)d_in[13];
    const float* beta    = (const float*)d_in[14];
    const float* rmean   = (const float*)d_in[15];
    const float* rvar    = (const float*)d_in[16];
    float* out = (float*)d_out;

    float *pSp, *pGp, *ph1, *pCs, *pA, *pnfdw, *pnfpw;
    cudaGetSymbolAddress((void**)&pSp, g_Sp);
    cudaGetSymbolAddress((void**)&pGp, g_Gp);
    cudaGetSymbolAddress((void**)&ph1, g_h1);
    cudaGetSymbolAddress((void**)&pCs, g_Cs);
    cudaGetSymbolAddress((void**)&pA, g_A);
    cudaGetSymbolAddress((void**)&pnfdw, g_nfdw);
    cudaGetSymbolAddress((void**)&pnfpw, g_nfpw);
    int *pidx0, *pidx1;
    cudaGetSymbolAddress((void**)&pidx0, g_idx0);
    cudaGetSymbolAddress((void**)&pidx1, g_idx1);

    // prep
    norms_kernel<<<dim3(NF, 4), 256>>>(cb_fdw, cb_fpw, cb_fdw2, cb_fpw2);
    quantw_kernel<<<1, 256>>>(dw_w1, pw_w1, dw_w2, pw_w2, cb_dw, cb_pw, cb_dw2, cb_pw2);
    shift_prep<<<dim3(NF, 9), 256>>>(cb_fdw2);

    // mega GEMM: VQ0 (z 0-3) + DOT1 (z 4-7) + G (z 8-34)
    mega_gemm<<<dim3(4, 4, 35), 256>>>(x, cb_fdw, cb_fpw, cb_fdw2, pCs, cb_fpw2, pSp, pGp);

    // VQ0 chain
    argmin_rows<<<BI, 256>>>(pSp, pnfdw, pidx0, 4);
    conv1_lrelu<<<BI, 256>>>(cb_fdw);

    // consume Gp (G partials) before VQ1 reuses the buffer
    pair_kernel<<<NF, 256>>>(3);

    // VQ1 (K=2116, 8 splits of 268) -> writes into Gp slices 0..7
    sgemm_nt<<<dim3(4, 4, 8), 256>>>(ph1, cb_fpw, pGp, D1, 268);
    argmin_rows<<<BI, 256>>>(pGp, pnfpw, pidx1, 8);

    // idx2 from DOT1 partials (Sp slices 4..7)
    idx2_kernel<<<BI, 256>>>(pSp + 4L * NN2, 4);

    // histogram -> A -> out GEMM (split-K 2, partials into Cs) -> BN reduce
    cnt_kernel<<<B_ * CH, 256>>>();
    A_kernel<<<BI, 256>>>();
    sgemm_nn_split<<<dim3(16, 4, 2), 256>>>(pA, cb_fpw2, pCs);
    bn_reduce<<<BI, 256>>>(pCs, out, gamma, beta, rmean, rvar);
}